// round 1
// baseline (speedup 1.0000x reference)
#include <cuda_runtime.h>
#include <cuda_bf16.h>
#include <math.h>

// Problem constants (fixed by the dataset)
#define NNODES 100000
#define EMAX   1700000
#define INDIM  128
#define HID    64
#define HEADS  4
#define Z1DIM  (HID*HEADS)   // 256
#define SCALES 3

// ---------------- device scratch ----------------
__device__ float d_Z1[(size_t)NNODES * Z1DIM];
__device__ float d_H1[(size_t)NNODES * Z1DIM];
__device__ float d_Z2[(size_t)NNODES * HID];
__device__ float d_S1src[NNODES * HEADS];
__device__ float d_S1dst[NNODES * HEADS];
__device__ float d_S2src[NNODES];
__device__ float d_S2dst[NNODES];
__device__ int   d_counts[NNODES];
__device__ int   d_cursor[NNODES];
__device__ int   d_offs[NNODES + 1];
__device__ int   d_esrc[EMAX];
__device__ int   d_blockSums[256];
__device__ int   d_blockOffs[256];
__device__ float d_sumH2[HID];
__device__ float d_fracsum[SCALES * INDIM];

// ---------------- helpers ----------------
__device__ __forceinline__ float lrelu(float x) { return x > 0.f ? x : 0.01f * x; }
__device__ __forceinline__ float elu1(float x)  { return x > 0.f ? x : expm1f(x); }

__device__ __forceinline__ unsigned long long fma2(unsigned long long a,
                                                   unsigned long long b,
                                                   unsigned long long c) {
    unsigned long long d;
    asm("fma.rn.f32x2 %0, %1, %2, %3;" : "=l"(d) : "l"(a), "l"(b), "l"(c));
    return d;
}
__device__ __forceinline__ unsigned long long pack2(float lo, float hi) {
    unsigned long long d;
    asm("mov.b64 %0, {%1,%2};" : "=l"(d) : "f"(lo), "f"(hi));
    return d;
}
__device__ __forceinline__ float2 unpack2(unsigned long long v) {
    float2 r;
    asm("mov.b64 {%0,%1}, %2;" : "=f"(r.x), "=f"(r.y) : "l"(v));
    return r;
}

// ---------------- zero scratch ----------------
__global__ void zero_kernel(int n) {
    int i = blockIdx.x * blockDim.x + threadIdx.x;
    if (i < n) { d_counts[i] = 0; d_cursor[i] = 0; }
    if (i < HID) d_sumH2[i] = 0.f;
    if (i < SCALES * INDIM) d_fracsum[i] = 0.f;
}

// ---------------- SGEMM: C[M,Nout] = A[M,K] * B[Nout,K]^T (f32x2 inner) ----------------
#define BM 128
#define BN 64
#define BK 16
__global__ __launch_bounds__(256) void sgemm_tn(const float* __restrict__ A,
                                                const float* __restrict__ B,
                                                float* __restrict__ C,
                                                int M, int K, int Nout) {
    __shared__ __align__(16) float As[BK][BM + 4];
    __shared__ __align__(16) float Bs[BK][BN + 4];
    int m0 = blockIdx.x * BM, n0 = blockIdx.y * BN;
    int tid = threadIdx.x;
    int r0 = (tid >> 4) * 8;   // 0..120
    int c0 = (tid & 15) * 4;   // 0..60

    unsigned long long acc[4][4];
#pragma unroll
    for (int i = 0; i < 4; i++)
#pragma unroll
        for (int j = 0; j < 4; j++) acc[i][j] = 0ull;

    int aRow = tid >> 1;             // 0..127
    int aCol = (tid & 1) * 8;        // 0 or 8
    int bRow = tid >> 2;             // 0..63
    int bCol = (tid & 3) * 4;        // 0..12

    for (int k0 = 0; k0 < K; k0 += BK) {
        float4 a0, a1;
        if (m0 + aRow < M) {
            const float* p = A + (size_t)(m0 + aRow) * K + k0 + aCol;
            a0 = *(const float4*)p;
            a1 = *(const float4*)(p + 4);
        } else {
            a0 = make_float4(0, 0, 0, 0);
            a1 = make_float4(0, 0, 0, 0);
        }
        As[aCol + 0][aRow] = a0.x; As[aCol + 1][aRow] = a0.y;
        As[aCol + 2][aRow] = a0.z; As[aCol + 3][aRow] = a0.w;
        As[aCol + 4][aRow] = a1.x; As[aCol + 5][aRow] = a1.y;
        As[aCol + 6][aRow] = a1.z; As[aCol + 7][aRow] = a1.w;

        const float* q = B + (size_t)(n0 + bRow) * K + k0 + bCol;
        float4 b0 = *(const float4*)q;
        Bs[bCol + 0][bRow] = b0.x; Bs[bCol + 1][bRow] = b0.y;
        Bs[bCol + 2][bRow] = b0.z; Bs[bCol + 3][bRow] = b0.w;
        __syncthreads();

#pragma unroll
        for (int k = 0; k < BK; k++) {
            unsigned long long ap[4];
#pragma unroll
            for (int i = 0; i < 4; i++)
                ap[i] = *(const unsigned long long*)&As[k][r0 + 2 * i];
#pragma unroll
            for (int j = 0; j < 4; j++) {
                float b = Bs[k][c0 + j];
                unsigned long long bb = pack2(b, b);
#pragma unroll
                for (int i = 0; i < 4; i++)
                    acc[i][j] = fma2(ap[i], bb, acc[i][j]);
            }
        }
        __syncthreads();
    }

#pragma unroll
    for (int i = 0; i < 4; i++) {
        float2 p0 = unpack2(acc[i][0]);
        float2 p1 = unpack2(acc[i][1]);
        float2 p2 = unpack2(acc[i][2]);
        float2 p3 = unpack2(acc[i][3]);
        int row0 = m0 + r0 + 2 * i;
        if (row0 < M) {
            float4 v = make_float4(p0.x, p1.x, p2.x, p3.x);
            *(float4*)&C[(size_t)row0 * Nout + n0 + c0] = v;
        }
        if (row0 + 1 < M) {
            float4 v = make_float4(p0.y, p1.y, p2.y, p3.y);
            *(float4*)&C[(size_t)(row0 + 1) * Nout + n0 + c0] = v;
        }
    }
}

// ---------------- attention pre-scores layer 1 ----------------
__global__ void s1_kernel(const float* __restrict__ attn, int n) {
    int w = (blockIdx.x * blockDim.x + threadIdx.x) >> 5;
    int lane = threadIdx.x & 31;
    if (w >= n) return;
    const float* z = d_Z1 + (size_t)w * Z1DIM;
#pragma unroll
    for (int h = 0; h < HEADS; h++) {
        float z0 = z[h * HID + lane], z1 = z[h * HID + 32 + lane];
        const float* a = attn + h * 2 * HID;
        float ps = z0 * a[lane] + z1 * a[32 + lane];
        float pd = z0 * a[HID + lane] + z1 * a[HID + 32 + lane];
#pragma unroll
        for (int o = 16; o; o >>= 1) {
            ps += __shfl_xor_sync(~0u, ps, o);
            pd += __shfl_xor_sync(~0u, pd, o);
        }
        if (lane == 0) { d_S1src[w * HEADS + h] = ps; d_S1dst[w * HEADS + h] = pd; }
    }
}

// ---------------- attention pre-scores layer 2 ----------------
__global__ void s2_kernel(const float* __restrict__ attn, int n) {
    int w = (blockIdx.x * blockDim.x + threadIdx.x) >> 5;
    int lane = threadIdx.x & 31;
    if (w >= n) return;
    const float* z = d_Z2 + (size_t)w * HID;
    float z0 = z[lane], z1 = z[32 + lane];
    float ps = z0 * attn[lane] + z1 * attn[32 + lane];
    float pd = z0 * attn[HID + lane] + z1 * attn[HID + 32 + lane];
#pragma unroll
    for (int o = 16; o; o >>= 1) {
        ps += __shfl_xor_sync(~0u, ps, o);
        pd += __shfl_xor_sync(~0u, pd, o);
    }
    if (lane == 0) { d_S2src[w] = ps; d_S2dst[w] = pd; }
}

// ---------------- CSR build ----------------
__global__ void hist_kernel(const int* __restrict__ dst, int e) {
    int i = blockIdx.x * blockDim.x + threadIdx.x;
    if (i < e) atomicAdd(&d_counts[dst[i]], 1);
}

__global__ void scan1_kernel(int n) {
    __shared__ int sm[1024];
    int i = blockIdx.x * 1024 + threadIdx.x;
    int x = (i < n) ? d_counts[i] : 0;
    sm[threadIdx.x] = x;
    __syncthreads();
    int val = x;
    for (int d = 1; d < 1024; d <<= 1) {
        int t = (threadIdx.x >= (unsigned)d) ? sm[threadIdx.x - d] : 0;
        __syncthreads();
        val += t;
        sm[threadIdx.x] = val;
        __syncthreads();
    }
    if (i < n) d_offs[i] = val - x;               // block-local exclusive
    if (threadIdx.x == 1023) d_blockSums[blockIdx.x] = val;
}

__global__ void scan2_kernel(int nb) {
    if (threadIdx.x == 0 && blockIdx.x == 0) {
        int acc = 0;
        for (int b = 0; b < nb; b++) { d_blockOffs[b] = acc; acc += d_blockSums[b]; }
    }
}

__global__ void scan3_kernel(int n, int e) {
    int i = blockIdx.x * blockDim.x + threadIdx.x;
    if (i < n) d_offs[i] += d_blockOffs[i >> 10];
    if (i == 0) d_offs[n] = e;
}

__global__ void fill_kernel(const int* __restrict__ src, const int* __restrict__ dst, int e) {
    int i = blockIdx.x * blockDim.x + threadIdx.x;
    if (i < e) {
        int d = dst[i];
        int pos = d_offs[d] + atomicAdd(&d_cursor[d], 1);
        d_esrc[pos] = src[i];
    }
}

// ---------------- layer1 GAT aggregation (4 heads fused), warp per dst ----------------
__global__ void agg1_kernel(int n) {
    int w = (blockIdx.x * blockDim.x + threadIdx.x) >> 5;
    int lane = threadIdx.x & 31;
    if (w >= n) return;
    int beg = d_offs[w], end = d_offs[w + 1];
    float4 sd4 = *(const float4*)(d_S1dst + w * 4);

    // phase 1: per-head max over incoming edges
    float m0 = -1e30f, m1 = -1e30f, m2 = -1e30f, m3 = -1e30f;
    for (int e = beg + lane; e < end; e += 32) {
        int s = d_esrc[e];
        float4 ss = __ldg((const float4*)(d_S1src + s * 4));
        m0 = fmaxf(m0, lrelu(ss.x + sd4.x));
        m1 = fmaxf(m1, lrelu(ss.y + sd4.y));
        m2 = fmaxf(m2, lrelu(ss.z + sd4.z));
        m3 = fmaxf(m3, lrelu(ss.w + sd4.w));
    }
#pragma unroll
    for (int o = 16; o; o >>= 1) {
        m0 = fmaxf(m0, __shfl_xor_sync(~0u, m0, o));
        m1 = fmaxf(m1, __shfl_xor_sync(~0u, m1, o));
        m2 = fmaxf(m2, __shfl_xor_sync(~0u, m2, o));
        m3 = fmaxf(m3, __shfl_xor_sync(~0u, m3, o));
    }

    int myh = lane >> 3;  // lanes 0-7 head 0, 8-15 head 1, ...
    float sd = (myh == 0) ? sd4.x : (myh == 1) ? sd4.y : (myh == 2) ? sd4.z : sd4.w;
    float mm = (myh == 0) ? m0 : (myh == 1) ? m1 : (myh == 2) ? m2 : m3;

    // phase 2: warp-serial over edges; lanes own 8 contiguous output cols
    float4 accA = make_float4(0, 0, 0, 0), accB = make_float4(0, 0, 0, 0);
    float den = 0.f;
    for (int e = beg; e < end; e++) {
        int s = d_esrc[e];                               // broadcast
        float sv = __ldg(d_S1src + s * 4 + myh);
        float wgt = __expf(lrelu(sv + sd) - mm);
        den += wgt;
        const float4* zp = (const float4*)(d_Z1 + (size_t)s * Z1DIM) + lane * 2;
        float4 za = __ldg(zp), zb = __ldg(zp + 1);
        accA.x += wgt * za.x; accA.y += wgt * za.y; accA.z += wgt * za.z; accA.w += wgt * za.w;
        accB.x += wgt * zb.x; accB.y += wgt * zb.y; accB.z += wgt * zb.z; accB.w += wgt * zb.w;
    }
    float inv = 1.f / den;
    float4 oa, ob;
    oa.x = elu1(accA.x * inv); oa.y = elu1(accA.y * inv);
    oa.z = elu1(accA.z * inv); oa.w = elu1(accA.w * inv);
    ob.x = elu1(accB.x * inv); ob.y = elu1(accB.y * inv);
    ob.z = elu1(accB.z * inv); ob.w = elu1(accB.w * inv);
    float* hp = d_H1 + (size_t)w * Z1DIM + lane * 8;
    *(float4*)hp = oa;
    *(float4*)(hp + 4) = ob;
}

// ---------------- layer2 GAT aggregation -> column sum directly ----------------
__global__ void agg2_kernel(int n) {
    __shared__ float red[HID];
    int lt = threadIdx.x;
    if (lt < HID) red[lt] = 0.f;
    __syncthreads();
    int w = (blockIdx.x * blockDim.x + lt) >> 5;
    int lane = lt & 31;
    if (w < n) {
        int beg = d_offs[w], end = d_offs[w + 1];
        float sd = d_S2dst[w];
        float m = -1e30f;
        for (int e = beg + lane; e < end; e += 32) {
            int s = d_esrc[e];
            m = fmaxf(m, lrelu(__ldg(d_S2src + s) + sd));
        }
#pragma unroll
        for (int o = 16; o; o >>= 1) m = fmaxf(m, __shfl_xor_sync(~0u, m, o));
        float2 acc = make_float2(0, 0);
        float den = 0.f;
        for (int e = beg; e < end; e++) {
            int s = d_esrc[e];
            float wgt = __expf(lrelu(__ldg(d_S2src + s) + sd) - m);
            den += wgt;
            float2 z = __ldg((const float2*)(d_Z2 + (size_t)s * HID) + lane);
            acc.x += wgt * z.x;
            acc.y += wgt * z.y;
        }
        float inv = 1.f / den;
        atomicAdd(&red[lane * 2 + 0], acc.x * inv);
        atomicAdd(&red[lane * 2 + 1], acc.y * inv);
    }
    __syncthreads();
    if (lt < HID) atomicAdd(&d_sumH2[lt], red[lt]);
}

// ---------------- fractal branch: sum of gathered h rows per scale ----------------
__global__ void frac_kernel(const float* __restrict__ h, const int* __restrict__ fcm, int n) {
    int s = blockIdx.y;
    __shared__ float red[INDIM];
    int lt = threadIdx.x;
    if (lt < INDIM) red[lt] = 0.f;
    __syncthreads();
    int lane = lt & 31;
    float4 acc = make_float4(0, 0, 0, 0);
    int wg = (blockIdx.x * blockDim.x + lt) >> 5;
    int nw = (gridDim.x * blockDim.x) >> 5;
    for (int node = wg; node < n; node += nw) {
        int idx = __ldg(fcm + node * SCALES + s);
        float4 v = __ldg((const float4*)(h + (size_t)idx * INDIM) + lane);
        acc.x += v.x; acc.y += v.y; acc.z += v.z; acc.w += v.w;
    }
    atomicAdd(&red[lane * 4 + 0], acc.x);
    atomicAdd(&red[lane * 4 + 1], acc.y);
    atomicAdd(&red[lane * 4 + 2], acc.z);
    atomicAdd(&red[lane * 4 + 3], acc.w);
    __syncthreads();
    if (lt < INDIM) atomicAdd(&d_fracsum[s * INDIM + lt], red[lt]);
}

// ---------------- final combine (all linear post-softmax work) ----------------
__global__ void final_kernel(const float* __restrict__ frac_w,
                             const float* __restrict__ frac_final_w,
                             const float* __restrict__ fc2_w,
                             float* __restrict__ out, int n) {
    __shared__ float y[SCALES * HID];   // mean of frac intermediate [192]
    __shared__ float mh[HID];           // mean of H2
    __shared__ float mf[HID];           // mean of h_frac
    int t = threadIdx.x;                // 64 threads
    float invn = 1.f / (float)n;
    mh[t] = d_sumH2[t] * invn;
#pragma unroll
    for (int s = 0; s < SCALES; s++) {
        const float* wrow = frac_w + (size_t)(s * HID + t) * INDIM;
        const float* g = d_fracsum + s * INDIM;
        float acc = 0.f;
        for (int k = 0; k < INDIM; k++) acc += wrow[k] * g[k];
        y[s * HID + t] = acc * invn;
    }
    __syncthreads();
    {
        const float* fr = frac_final_w + (size_t)t * (SCALES * HID);
        float acc = 0.f;
        for (int k = 0; k < SCALES * HID; k++) acc += fr[k] * y[k];
        mf[t] = acc;
    }
    __syncthreads();
    {
        const float* w2 = fc2_w + (size_t)t * (2 * HID);
        float o = 0.f;
        for (int k = 0; k < HID; k++) o += w2[k] * mh[k];
        for (int k = 0; k < HID; k++) o += w2[HID + k] * mf[k];
        out[t] = o;
    }
}

// ---------------- launch ----------------
extern "C" void kernel_launch(void* const* d_in, const int* in_sizes, int n_in,
                              void* d_out, int out_size) {
    const float* h      = (const float*)d_in[0];
    const int*   src    = (const int*)d_in[1];
    const int*   dst    = (const int*)d_in[2];
    const int*   fcm    = (const int*)d_in[3];
    const float* l1fc   = (const float*)d_in[4];  // [4,64,128] -> [256,128]
    const float* l1attn = (const float*)d_in[5];  // [4,128]
    const float* l2fc   = (const float*)d_in[6];  // [64,256]
    const float* l2attn = (const float*)d_in[7];  // [128]
    const float* frw    = (const float*)d_in[8];  // [3,64,128]
    const float* frfw   = (const float*)d_in[9];  // [64,192]
    const float* fc2    = (const float*)d_in[10]; // [64,128]
    float* out = (float*)d_out;

    int n = in_sizes[0] / INDIM;   // 100000
    int e = in_sizes[1];           // 1700000

    float *z1p, *h1p, *z2p;
    cudaGetSymbolAddress((void**)&z1p, d_Z1);
    cudaGetSymbolAddress((void**)&h1p, d_H1);
    cudaGetSymbolAddress((void**)&z2p, d_Z2);

    int tpb = 256;
    int nWarpBlocks = (n * 32 + tpb - 1) / tpb;
    int nEdgeBlocks = (e + tpb - 1) / tpb;
    int nNodeBlocks = (n + tpb - 1) / tpb;
    int nb = (n + 1023) / 1024;

    // 0. zero scratch (counts/cursor/sums)
    zero_kernel<<<nNodeBlocks, tpb>>>(n);

    // 1. Z1 = h @ W1cat^T   [n,128] x [256,128]^T
    {
        dim3 grid((n + BM - 1) / BM, Z1DIM / BN);
        sgemm_tn<<<grid, 256>>>(h, l1fc, z1p, n, INDIM, Z1DIM);
    }

    // 2. per-node attention pre-scores (layer 1)
    s1_kernel<<<nWarpBlocks, tpb>>>(l1attn, n);

    // 3. CSR build (sorted by dst)
    hist_kernel<<<nEdgeBlocks, tpb>>>(dst, e);
    scan1_kernel<<<nb, 1024>>>(n);
    scan2_kernel<<<1, 32>>>(nb);
    scan3_kernel<<<nNodeBlocks, tpb>>>(n, e);
    fill_kernel<<<nEdgeBlocks, tpb>>>(src, dst, e);

    // 4. layer-1 GAT aggregation -> H1 (elu applied)
    agg1_kernel<<<nWarpBlocks, tpb>>>(n);

    // 5. Z2 = H1 @ layer2_fc^T   [n,256] x [64,256]^T
    {
        dim3 grid((n + BM - 1) / BM, HID / BN);
        sgemm_tn<<<grid, 256>>>(h1p, l2fc, z2p, n, Z1DIM, HID);
    }

    // 6. per-node attention pre-scores (layer 2)
    s2_kernel<<<nWarpBlocks, tpb>>>(l2attn, n);

    // 7. layer-2 GAT aggregation -> column sums of H2 only
    agg2_kernel<<<nWarpBlocks, tpb>>>(n);

    // 8. fractal branch gather-sums
    {
        dim3 grid(128, SCALES);
        frac_kernel<<<grid, tpb>>>(h, fcm, n);
    }

    // 9. final linear combine + mean
    final_kernel<<<1, HID>>>(frw, frfw, fc2, out, n);
}

// round 2
// speedup vs baseline: 1.0968x; 1.0968x over previous
#include <cuda_runtime.h>
#include <cuda_fp16.h>
#include <math.h>

// Problem constants (fixed by the dataset)
#define NNODES 100000
#define EMAX   1700000
#define INDIM  128
#define HID    64
#define HEADS  4
#define Z1DIM  (HID*HEADS)   // 256
#define SCALES 3

// ---------------- device scratch ----------------
__device__ __align__(16) __half d_Z1h[(size_t)NNODES * Z1DIM];
__device__ __align__(16) __half d_H1h[(size_t)NNODES * Z1DIM];
__device__ __align__(16) __half d_Z2h[(size_t)NNODES * HID];
__device__ float d_S1src[NNODES * HEADS];
__device__ float d_S1dst[NNODES * HEADS];
__device__ float d_S2src[NNODES];
__device__ float d_S2dst[NNODES];
__device__ int   d_counts[NNODES];
__device__ int   d_cursor[NNODES];
__device__ int   d_offs[NNODES + 1];
__device__ int   d_esrc[EMAX];
__device__ int   d_blockSums[256];
__device__ int   d_blockOffs[256];
__device__ float d_sumH2[HID];
__device__ float d_fracsum[SCALES * INDIM];

// ---------------- helpers ----------------
__device__ __forceinline__ float lrelu(float x) { return x > 0.f ? x : 0.01f * x; }
__device__ __forceinline__ float elu1(float x)  { return x > 0.f ? x : expm1f(x); }

__device__ __forceinline__ unsigned long long fma2(unsigned long long a,
                                                   unsigned long long b,
                                                   unsigned long long c) {
    unsigned long long d;
    asm("fma.rn.f32x2 %0, %1, %2, %3;" : "=l"(d) : "l"(a), "l"(b), "l"(c));
    return d;
}
__device__ __forceinline__ unsigned long long pack2(float lo, float hi) {
    unsigned long long d;
    asm("mov.b64 %0, {%1,%2};" : "=l"(d) : "f"(lo), "f"(hi));
    return d;
}
__device__ __forceinline__ float2 unpack2(unsigned long long v) {
    float2 r;
    asm("mov.b64 {%0,%1}, %2;" : "=f"(r.x), "=f"(r.y) : "l"(v));
    return r;
}

// ---------------- zero scratch ----------------
__global__ void zero_kernel(int n) {
    int i = blockIdx.x * blockDim.x + threadIdx.x;
    if (i < n) d_counts[i] = 0;
    if (i < HID) d_sumH2[i] = 0.f;
    if (i < SCALES * INDIM) d_fracsum[i] = 0.f;
}

// ---------------- SGEMM: C[M,Nout](half) = A[M,K] * B[Nout,K]^T ----------------
#define BM 128
#define BN 64
#define BK 16
template <typename TA>
__global__ __launch_bounds__(256) void sgemm_tn(const TA* __restrict__ A,
                                                const float* __restrict__ B,
                                                __half* __restrict__ C,
                                                int M, int K, int Nout) {
    __shared__ __align__(16) float As[BK][BM + 4];
    __shared__ __align__(16) float Bs[BK][BN + 4];
    int m0 = blockIdx.x * BM, n0 = blockIdx.y * BN;
    int tid = threadIdx.x;
    int r0 = (tid >> 4) * 8;   // 0..120
    int c0 = (tid & 15) * 4;   // 0..60

    unsigned long long acc[4][4];
#pragma unroll
    for (int i = 0; i < 4; i++)
#pragma unroll
        for (int j = 0; j < 4; j++) acc[i][j] = 0ull;

    int aRow = tid >> 1;             // 0..127
    int aCol = (tid & 1) * 8;        // 0 or 8
    int bRow = tid >> 2;             // 0..63
    int bCol = (tid & 3) * 4;        // 0..12

    for (int k0 = 0; k0 < K; k0 += BK) {
        float av[8];
        if (m0 + aRow < M) {
            const TA* p = A + (size_t)(m0 + aRow) * K + k0 + aCol;
            if constexpr (sizeof(TA) == 4) {
                float4 a0 = *(const float4*)p;
                float4 a1 = *(const float4*)(p + 4);
                av[0] = a0.x; av[1] = a0.y; av[2] = a0.z; av[3] = a0.w;
                av[4] = a1.x; av[5] = a1.y; av[6] = a1.z; av[7] = a1.w;
            } else {
                uint4 u = *(const uint4*)p;   // 8 halves
                const __half2* hp = (const __half2*)&u;
#pragma unroll
                for (int q = 0; q < 4; q++) {
                    float2 f = __half22float2(hp[q]);
                    av[2 * q] = f.x; av[2 * q + 1] = f.y;
                }
            }
        } else {
#pragma unroll
            for (int q = 0; q < 8; q++) av[q] = 0.f;
        }
#pragma unroll
        for (int q = 0; q < 8; q++) As[aCol + q][aRow] = av[q];

        const float* qb = B + (size_t)(n0 + bRow) * K + k0 + bCol;
        float4 b0 = *(const float4*)qb;
        Bs[bCol + 0][bRow] = b0.x; Bs[bCol + 1][bRow] = b0.y;
        Bs[bCol + 2][bRow] = b0.z; Bs[bCol + 3][bRow] = b0.w;
        __syncthreads();

#pragma unroll
        for (int k = 0; k < BK; k++) {
            unsigned long long ap[4];
#pragma unroll
            for (int i = 0; i < 4; i++)
                ap[i] = *(const unsigned long long*)&As[k][r0 + 2 * i];
#pragma unroll
            for (int j = 0; j < 4; j++) {
                float b = Bs[k][c0 + j];
                unsigned long long bb = pack2(b, b);
#pragma unroll
                for (int i = 0; i < 4; i++)
                    acc[i][j] = fma2(ap[i], bb, acc[i][j]);
            }
        }
        __syncthreads();
    }

#pragma unroll
    for (int i = 0; i < 4; i++) {
        float2 p0 = unpack2(acc[i][0]);
        float2 p1 = unpack2(acc[i][1]);
        float2 p2 = unpack2(acc[i][2]);
        float2 p3 = unpack2(acc[i][3]);
        int row0 = m0 + r0 + 2 * i;
        if (row0 < M) {
            __half2 lo = __halves2half2(__float2half_rn(p0.x), __float2half_rn(p1.x));
            __half2 hi = __halves2half2(__float2half_rn(p2.x), __float2half_rn(p3.x));
            uint2 v = make_uint2(*(unsigned*)&lo, *(unsigned*)&hi);
            *(uint2*)&C[(size_t)row0 * Nout + n0 + c0] = v;
        }
        if (row0 + 1 < M) {
            __half2 lo = __halves2half2(__float2half_rn(p0.y), __float2half_rn(p1.y));
            __half2 hi = __halves2half2(__float2half_rn(p2.y), __float2half_rn(p3.y));
            uint2 v = make_uint2(*(unsigned*)&lo, *(unsigned*)&hi);
            *(uint2*)&C[(size_t)(row0 + 1) * Nout + n0 + c0] = v;
        }
    }
}

// ---------------- attention pre-scores layer 1 ----------------
__global__ void s1_kernel(const float* __restrict__ attn, int n) {
    int w = (blockIdx.x * blockDim.x + threadIdx.x) >> 5;
    int lane = threadIdx.x & 31;
    if (w >= n) return;
    const __half* z = d_Z1h + (size_t)w * Z1DIM;
#pragma unroll
    for (int h = 0; h < HEADS; h++) {
        float z0 = __half2float(z[h * HID + lane]);
        float z1 = __half2float(z[h * HID + 32 + lane]);
        const float* a = attn + h * 2 * HID;
        float ps = z0 * a[lane] + z1 * a[32 + lane];
        float pd = z0 * a[HID + lane] + z1 * a[HID + 32 + lane];
#pragma unroll
        for (int o = 16; o; o >>= 1) {
            ps += __shfl_xor_sync(~0u, ps, o);
            pd += __shfl_xor_sync(~0u, pd, o);
        }
        if (lane == 0) { d_S1src[w * HEADS + h] = ps; d_S1dst[w * HEADS + h] = pd; }
    }
}

// ---------------- attention pre-scores layer 2 ----------------
__global__ void s2_kernel(const float* __restrict__ attn, int n) {
    int w = (blockIdx.x * blockDim.x + threadIdx.x) >> 5;
    int lane = threadIdx.x & 31;
    if (w >= n) return;
    const __half* z = d_Z2h + (size_t)w * HID;
    float z0 = __half2float(z[lane]);
    float z1 = __half2float(z[32 + lane]);
    float ps = z0 * attn[lane] + z1 * attn[32 + lane];
    float pd = z0 * attn[HID + lane] + z1 * attn[HID + 32 + lane];
#pragma unroll
    for (int o = 16; o; o >>= 1) {
        ps += __shfl_xor_sync(~0u, ps, o);
        pd += __shfl_xor_sync(~0u, pd, o);
    }
    if (lane == 0) { d_S2src[w] = ps; d_S2dst[w] = pd; }
}

// ---------------- CSR build ----------------
__global__ void hist_kernel(const int* __restrict__ dst, int e) {
    int i = blockIdx.x * blockDim.x + threadIdx.x;
    if (i < e) atomicAdd(&d_counts[dst[i]], 1);
}

__global__ void scan1_kernel(int n) {
    __shared__ int sm[1024];
    int i = blockIdx.x * 1024 + threadIdx.x;
    int x = (i < n) ? d_counts[i] : 0;
    sm[threadIdx.x] = x;
    __syncthreads();
    int val = x;
    for (int d = 1; d < 1024; d <<= 1) {
        int t = (threadIdx.x >= (unsigned)d) ? sm[threadIdx.x - d] : 0;
        __syncthreads();
        val += t;
        sm[threadIdx.x] = val;
        __syncthreads();
    }
    if (i < n) d_offs[i] = val - x;               // block-local exclusive
    if (threadIdx.x == 1023) d_blockSums[blockIdx.x] = val;
}

__global__ void scan2_kernel(int nb) {
    if (threadIdx.x == 0 && blockIdx.x == 0) {
        int acc = 0;
        for (int b = 0; b < nb; b++) { d_blockOffs[b] = acc; acc += d_blockSums[b]; }
    }
}

__global__ void scan3_kernel(int n, int e) {
    int i = blockIdx.x * blockDim.x + threadIdx.x;
    if (i < n) {
        int o = d_offs[i] + d_blockOffs[i >> 10];
        d_offs[i] = o;
        d_cursor[i] = o;   // pre-seeded cursor: fill uses a single atomic
    }
    if (i == 0) d_offs[n] = e;
}

__global__ void fill_kernel(const int* __restrict__ src, const int* __restrict__ dst, int e) {
    int i = blockIdx.x * blockDim.x + threadIdx.x;
    if (i < e) {
        int pos = atomicAdd(&d_cursor[dst[i]], 1);
        d_esrc[pos] = src[i];
    }
}

// ---------------- layer1 GAT aggregation (4 heads fused), warp per dst ----------------
__global__ void agg1_kernel(int n) {
    int w = (blockIdx.x * blockDim.x + threadIdx.x) >> 5;
    int lane = threadIdx.x & 31;
    if (w >= n) return;
    int beg = d_offs[w], end = d_offs[w + 1];
    float4 sd4 = *(const float4*)(d_S1dst + w * 4);

    // phase 1: per-head max over incoming edges
    float m0 = -1e30f, m1 = -1e30f, m2 = -1e30f, m3 = -1e30f;
    for (int e = beg + lane; e < end; e += 32) {
        int s = d_esrc[e];
        float4 ss = __ldg((const float4*)(d_S1src + s * 4));
        m0 = fmaxf(m0, lrelu(ss.x + sd4.x));
        m1 = fmaxf(m1, lrelu(ss.y + sd4.y));
        m2 = fmaxf(m2, lrelu(ss.z + sd4.z));
        m3 = fmaxf(m3, lrelu(ss.w + sd4.w));
    }
#pragma unroll
    for (int o = 16; o; o >>= 1) {
        m0 = fmaxf(m0, __shfl_xor_sync(~0u, m0, o));
        m1 = fmaxf(m1, __shfl_xor_sync(~0u, m1, o));
        m2 = fmaxf(m2, __shfl_xor_sync(~0u, m2, o));
        m3 = fmaxf(m3, __shfl_xor_sync(~0u, m3, o));
    }

    int myh = lane >> 3;  // lanes 0-7 head 0, 8-15 head 1, ...
    float sd = (myh == 0) ? sd4.x : (myh == 1) ? sd4.y : (myh == 2) ? sd4.z : sd4.w;
    float mm = (myh == 0) ? m0 : (myh == 1) ? m1 : (myh == 2) ? m2 : m3;

    // phase 2: warp-serial over edges; lanes own 8 contiguous output cols (halves)
    float acc[8] = {0, 0, 0, 0, 0, 0, 0, 0};
    float den = 0.f;
    for (int e = beg; e < end; e++) {
        int s = d_esrc[e];                               // broadcast
        float sv = __ldg(d_S1src + s * 4 + myh);
        float wgt = __expf(lrelu(sv + sd) - mm);
        den += wgt;
        uint4 u = __ldg((const uint4*)(d_Z1h + (size_t)s * Z1DIM) + lane);  // 8 halves
        const __half2* hp = (const __half2*)&u;
#pragma unroll
        for (int q = 0; q < 4; q++) {
            float2 f = __half22float2(hp[q]);
            acc[2 * q]     += wgt * f.x;
            acc[2 * q + 1] += wgt * f.y;
        }
    }
    float inv = 1.f / den;
    uint4 outv;
    __half2* op = (__half2*)&outv;
#pragma unroll
    for (int q = 0; q < 4; q++) {
        float a = elu1(acc[2 * q] * inv);
        float b = elu1(acc[2 * q + 1] * inv);
        op[q] = __halves2half2(__float2half_rn(a), __float2half_rn(b));
    }
    *((uint4*)(d_H1h + (size_t)w * Z1DIM) + lane) = outv;
}

// ---------------- layer2 GAT aggregation -> column sum directly ----------------
__global__ void agg2_kernel(int n) {
    __shared__ float red[HID];
    int lt = threadIdx.x;
    if (lt < HID) red[lt] = 0.f;
    __syncthreads();
    int w = (blockIdx.x * blockDim.x + lt) >> 5;
    int lane = lt & 31;
    if (w < n) {
        int beg = d_offs[w], end = d_offs[w + 1];
        float sd = d_S2dst[w];
        float m = -1e30f;
        for (int e = beg + lane; e < end; e += 32) {
            int s = d_esrc[e];
            m = fmaxf(m, lrelu(__ldg(d_S2src + s) + sd));
        }
#pragma unroll
        for (int o = 16; o; o >>= 1) m = fmaxf(m, __shfl_xor_sync(~0u, m, o));
        float2 acc = make_float2(0, 0);
        float den = 0.f;
        for (int e = beg; e < end; e++) {
            int s = d_esrc[e];
            float wgt = __expf(lrelu(__ldg(d_S2src + s) + sd) - m);
            den += wgt;
            __half2 zh = __ldg((const __half2*)(d_Z2h + (size_t)s * HID) + lane);
            float2 z = __half22float2(zh);
            acc.x += wgt * z.x;
            acc.y += wgt * z.y;
        }
        float inv = 1.f / den;
        atomicAdd(&red[lane * 2 + 0], acc.x * inv);
        atomicAdd(&red[lane * 2 + 1], acc.y * inv);
    }
    __syncthreads();
    if (lt < HID) atomicAdd(&d_sumH2[lt], red[lt]);
}

// ---------------- fractal branch: sum of gathered h rows per scale ----------------
__global__ void frac_kernel(const float* __restrict__ h, const int* __restrict__ fcm, int n) {
    int s = blockIdx.y;
    __shared__ float red[INDIM];
    int lt = threadIdx.x;
    if (lt < INDIM) red[lt] = 0.f;
    __syncthreads();
    int lane = lt & 31;
    float4 acc = make_float4(0, 0, 0, 0);
    int wg = (blockIdx.x * blockDim.x + lt) >> 5;
    int nw = (gridDim.x * blockDim.x) >> 5;
    for (int node = wg; node < n; node += nw) {
        int idx = __ldg(fcm + node * SCALES + s);
        float4 v = __ldg((const float4*)(h + (size_t)idx * INDIM) + lane);
        acc.x += v.x; acc.y += v.y; acc.z += v.z; acc.w += v.w;
    }
    atomicAdd(&red[lane * 4 + 0], acc.x);
    atomicAdd(&red[lane * 4 + 1], acc.y);
    atomicAdd(&red[lane * 4 + 2], acc.z);
    atomicAdd(&red[lane * 4 + 3], acc.w);
    __syncthreads();
    if (lt < INDIM) atomicAdd(&d_fracsum[s * INDIM + lt], red[lt]);
}

// ---------------- final combine (all linear post-softmax work) ----------------
__global__ void final_kernel(const float* __restrict__ frac_w,
                             const float* __restrict__ frac_final_w,
                             const float* __restrict__ fc2_w,
                             float* __restrict__ out, int n) {
    __shared__ float y[SCALES * HID];   // mean of frac intermediate [192]
    __shared__ float mh[HID];           // mean of H2
    __shared__ float mf[HID];           // mean of h_frac
    int t = threadIdx.x;                // 64 threads
    float invn = 1.f / (float)n;
    mh[t] = d_sumH2[t] * invn;
#pragma unroll
    for (int s = 0; s < SCALES; s++) {
        const float* wrow = frac_w + (size_t)(s * HID + t) * INDIM;
        const float* g = d_fracsum + s * INDIM;
        float acc = 0.f;
        for (int k = 0; k < INDIM; k++) acc += wrow[k] * g[k];
        y[s * HID + t] = acc * invn;
    }
    __syncthreads();
    {
        const float* fr = frac_final_w + (size_t)t * (SCALES * HID);
        float acc = 0.f;
        for (int k = 0; k < SCALES * HID; k++) acc += fr[k] * y[k];
        mf[t] = acc;
    }
    __syncthreads();
    {
        const float* w2 = fc2_w + (size_t)t * (2 * HID);
        float o = 0.f;
        for (int k = 0; k < HID; k++) o += w2[k] * mh[k];
        for (int k = 0; k < HID; k++) o += w2[HID + k] * mf[k];
        out[t] = o;
    }
}

// ---------------- launch ----------------
extern "C" void kernel_launch(void* const* d_in, const int* in_sizes, int n_in,
                              void* d_out, int out_size) {
    const float* h      = (const float*)d_in[0];
    const int*   src    = (const int*)d_in[1];
    const int*   dst    = (const int*)d_in[2];
    const int*   fcm    = (const int*)d_in[3];
    const float* l1fc   = (const float*)d_in[4];  // [4,64,128] -> [256,128]
    const float* l1attn = (const float*)d_in[5];  // [4,128]
    const float* l2fc   = (const float*)d_in[6];  // [64,256]
    const float* l2attn = (const float*)d_in[7];  // [128]
    const float* frw    = (const float*)d_in[8];  // [3,64,128]
    const float* frfw   = (const float*)d_in[9];  // [64,192]
    const float* fc2    = (const float*)d_in[10]; // [64,128]
    float* out = (float*)d_out;

    int n = in_sizes[0] / INDIM;   // 100000
    int e = in_sizes[1];           // 1700000

    __half *z1p, *h1p, *z2p;
    cudaGetSymbolAddress((void**)&z1p, d_Z1h);
    cudaGetSymbolAddress((void**)&h1p, d_H1h);
    cudaGetSymbolAddress((void**)&z2p, d_Z2h);

    int tpb = 256;
    int nWarpBlocks = (n * 32 + tpb - 1) / tpb;
    int nEdgeBlocks = (e + tpb - 1) / tpb;
    int nNodeBlocks = (n + tpb - 1) / tpb;
    int nb = (n + 1023) / 1024;

    // 0. zero scratch (counts/sums)
    zero_kernel<<<nNodeBlocks, tpb>>>(n);

    // 1. Z1 = h @ W1cat^T   [n,128] x [256,128]^T  (fp16 out)
    {
        dim3 grid((n + BM - 1) / BM, Z1DIM / BN);
        sgemm_tn<float><<<grid, 256>>>(h, l1fc, z1p, n, INDIM, Z1DIM);
    }

    // 2. per-node attention pre-scores (layer 1)
    s1_kernel<<<nWarpBlocks, tpb>>>(l1attn, n);

    // 3. CSR build (sorted by dst)
    hist_kernel<<<nEdgeBlocks, tpb>>>(dst, e);
    scan1_kernel<<<nb, 1024>>>(n);
    scan2_kernel<<<1, 32>>>(nb);
    scan3_kernel<<<nNodeBlocks, tpb>>>(n, e);
    fill_kernel<<<nEdgeBlocks, tpb>>>(src, dst, e);

    // 4. layer-1 GAT aggregation -> H1 (elu applied, fp16)
    agg1_kernel<<<nWarpBlocks, tpb>>>(n);

    // 5. Z2 = H1 @ layer2_fc^T   [n,256] x [64,256]^T  (fp16 in/out)
    {
        dim3 grid((n + BM - 1) / BM, HID / BN);
        sgemm_tn<__half><<<grid, 256>>>(h1p, l2fc, z2p, n, Z1DIM, HID);
    }

    // 6. per-node attention pre-scores (layer 2)
    s2_kernel<<<nWarpBlocks, tpb>>>(l2attn, n);

    // 7. layer-2 GAT aggregation -> column sums of H2 only
    agg2_kernel<<<nWarpBlocks, tpb>>>(n);

    // 8. fractal branch gather-sums
    {
        dim3 grid(128, SCALES);
        frac_kernel<<<grid, tpb>>>(h, fcm, n);
    }

    // 9. final linear combine + mean
    final_kernel<<<1, HID>>>(frw, frfw, fc2, out, n);
}

// round 3
// speedup vs baseline: 1.6624x; 1.5157x over previous
#include <cuda_runtime.h>
#include <cuda_fp16.h>
#include <math.h>

// Problem constants (fixed by the dataset)
#define NNODES 100000
#define EMAX   1700000
#define INDIM  128
#define HID    64
#define HEADS  4
#define Z1DIM  (HID*HEADS)   // 256
#define SCALES 3

// ---------------- device scratch ----------------
__device__ __align__(16) __half d_Z1h[(size_t)NNODES * Z1DIM];
__device__ __align__(16) __half d_H1h[(size_t)NNODES * Z1DIM];
__device__ __align__(16) __half d_Z2h[(size_t)NNODES * HID];
__device__ float d_S1src[NNODES * HEADS];
__device__ float d_S1dst[NNODES * HEADS];
__device__ float d_S2src[NNODES];
__device__ float d_S2dst[NNODES];
__device__ int   d_counts[NNODES];
__device__ int   d_cursor[NNODES];
__device__ int   d_offs[NNODES + 1];
__device__ int   d_esrc[EMAX];
__device__ int   d_blockSums[256];
__device__ int   d_blockOffs[256];
__device__ float d_sumH2[HID];
__device__ float d_fracsum[SCALES * INDIM];

// ---------------- helpers ----------------
__device__ __forceinline__ float lrelu(float x) { return x > 0.f ? x : 0.01f * x; }
__device__ __forceinline__ float elu1(float x)  { return x > 0.f ? x : expm1f(x); }

// ---------------- zero scratch ----------------
__global__ void zero_kernel(int n) {
    int i = blockIdx.x * blockDim.x + threadIdx.x;
    if (i < n) d_counts[i] = 0;
    if (i < HID) d_sumH2[i] = 0.f;
    if (i < SCALES * INDIM) d_fracsum[i] = 0.f;
}

// ---------------- Tensor-core GEMM: C[M,BN](half) = A[M,KK] * B[BN,KK]^T ----------------
// Whole K and whole N held in shared memory; one cooperative load, then MMA sweep.
// 256 threads = 8 warps arranged (BM/32) x (BN/WN).
template <int BM, int BN, int KK, typename TA>
__global__ __launch_bounds__(256) void gemm_tc(const TA* __restrict__ A,
                                               const float* __restrict__ B,
                                               __half* __restrict__ C,
                                               int M) {
    constexpr int LDA = KK + 8;                 // halves, pad for conflict-free frag loads
    constexpr int M_WARPS = BM / 32;            // warps along M
    constexpr int N_WARPS = 8 / M_WARPS;        // warps along N
    constexpr int WN = BN / N_WARPS;            // warp tile N width
    constexpr int M_FRAGS = 2;                  // 32 / 16
    constexpr int N_FRAGS = WN / 8;

    extern __shared__ __half smem[];
    __half* As = smem;                          // [BM][LDA]
    __half* Bs = smem + BM * LDA;               // [BN][LDA]

    int tid = threadIdx.x;
    int lane = tid & 31;
    int wid = tid >> 5;
    int wm = (wid % M_WARPS) * 32;
    int wn = (wid / M_WARPS) * WN;
    int m0 = blockIdx.x * BM;

    // ---- cooperative load A tile (convert to half) ----
    constexpr int A_ITERS = BM * KK / (256 * 8);
#pragma unroll
    for (int it = 0; it < A_ITERS; it++) {
        int idx = (it * 256 + tid) * 8;
        int row = idx / KK, col = idx % KK;
        int grow = m0 + row;
        uint4 u;
        if (grow < M) {
            if constexpr (sizeof(TA) == 4) {
                const float* p = (const float*)A + (size_t)grow * KK + col;
                float4 v0 = *(const float4*)p;
                float4 v1 = *(const float4*)(p + 4);
                __half2 h0 = __floats2half2_rn(v0.x, v0.y);
                __half2 h1 = __floats2half2_rn(v0.z, v0.w);
                __half2 h2 = __floats2half2_rn(v1.x, v1.y);
                __half2 h3 = __floats2half2_rn(v1.z, v1.w);
                u = make_uint4(*(unsigned*)&h0, *(unsigned*)&h1, *(unsigned*)&h2, *(unsigned*)&h3);
            } else {
                u = *(const uint4*)((const __half*)A + (size_t)grow * KK + col);
            }
        } else {
            u = make_uint4(0, 0, 0, 0);
        }
        *(uint4*)&As[row * LDA + col] = u;
    }

    // ---- cooperative load B tile (fp32 weights -> half) ----
    constexpr int B_ITERS = BN * KK / (256 * 8);
#pragma unroll
    for (int it = 0; it < B_ITERS; it++) {
        int idx = (it * 256 + tid) * 8;
        int row = idx / KK, col = idx % KK;
        const float* p = B + (size_t)row * KK + col;
        float4 v0 = *(const float4*)p;
        float4 v1 = *(const float4*)(p + 4);
        __half2 h0 = __floats2half2_rn(v0.x, v0.y);
        __half2 h1 = __floats2half2_rn(v0.z, v0.w);
        __half2 h2 = __floats2half2_rn(v1.x, v1.y);
        __half2 h3 = __floats2half2_rn(v1.z, v1.w);
        *(uint4*)&Bs[row * LDA + col] = make_uint4(*(unsigned*)&h0, *(unsigned*)&h1,
                                                   *(unsigned*)&h2, *(unsigned*)&h3);
    }
    __syncthreads();

    float acc[M_FRAGS][N_FRAGS][4];
#pragma unroll
    for (int f = 0; f < M_FRAGS; f++)
#pragma unroll
        for (int g = 0; g < N_FRAGS; g++)
#pragma unroll
            for (int q = 0; q < 4; q++) acc[f][g][q] = 0.f;

    int lr = lane >> 2;
    int lc = (lane & 3) * 2;

#pragma unroll
    for (int ks = 0; ks < KK / 16; ks++) {
        unsigned a[M_FRAGS][4];
#pragma unroll
        for (int f = 0; f < M_FRAGS; f++) {
            const __half* pa = As + (wm + f * 16 + lr) * LDA + ks * 16 + lc;
            a[f][0] = *(const unsigned*)pa;
            a[f][1] = *(const unsigned*)(pa + 8 * LDA);
            a[f][2] = *(const unsigned*)(pa + 8);
            a[f][3] = *(const unsigned*)(pa + 8 * LDA + 8);
        }
        unsigned b[N_FRAGS][2];
#pragma unroll
        for (int g = 0; g < N_FRAGS; g++) {
            const __half* pb = Bs + (wn + g * 8 + lr) * LDA + ks * 16 + lc;
            b[g][0] = *(const unsigned*)pb;
            b[g][1] = *(const unsigned*)(pb + 8);
        }
#pragma unroll
        for (int f = 0; f < M_FRAGS; f++)
#pragma unroll
            for (int g = 0; g < N_FRAGS; g++) {
                asm volatile(
                    "mma.sync.aligned.m16n8k16.row.col.f32.f16.f16.f32 "
                    "{%0,%1,%2,%3}, {%4,%5,%6,%7}, {%8,%9}, {%0,%1,%2,%3};"
                    : "+f"(acc[f][g][0]), "+f"(acc[f][g][1]),
                      "+f"(acc[f][g][2]), "+f"(acc[f][g][3])
                    : "r"(a[f][0]), "r"(a[f][1]), "r"(a[f][2]), "r"(a[f][3]),
                      "r"(b[g][0]), "r"(b[g][1]));
            }
    }

    // ---- epilogue: fp32 acc -> fp16 C ----
#pragma unroll
    for (int f = 0; f < M_FRAGS; f++) {
        int row = m0 + wm + f * 16 + lr;
#pragma unroll
        for (int g = 0; g < N_FRAGS; g++) {
            int col = wn + g * 8 + lc;
            if (row < M) {
                __half2 v = __floats2half2_rn(acc[f][g][0], acc[f][g][1]);
                *(__half2*)&C[(size_t)row * BN + col] = v;
            }
            if (row + 8 < M) {
                __half2 v = __floats2half2_rn(acc[f][g][2], acc[f][g][3]);
                *(__half2*)&C[(size_t)(row + 8) * BN + col] = v;
            }
        }
    }
}

// ---------------- attention pre-scores layer 1 ----------------
__global__ void s1_kernel(const float* __restrict__ attn, int n) {
    int w = (blockIdx.x * blockDim.x + threadIdx.x) >> 5;
    int lane = threadIdx.x & 31;
    if (w >= n) return;
    const __half* z = d_Z1h + (size_t)w * Z1DIM;
#pragma unroll
    for (int h = 0; h < HEADS; h++) {
        float z0 = __half2float(z[h * HID + lane]);
        float z1 = __half2float(z[h * HID + 32 + lane]);
        const float* a = attn + h * 2 * HID;
        float ps = z0 * a[lane] + z1 * a[32 + lane];
        float pd = z0 * a[HID + lane] + z1 * a[HID + 32 + lane];
#pragma unroll
        for (int o = 16; o; o >>= 1) {
            ps += __shfl_xor_sync(~0u, ps, o);
            pd += __shfl_xor_sync(~0u, pd, o);
        }
        if (lane == 0) { d_S1src[w * HEADS + h] = ps; d_S1dst[w * HEADS + h] = pd; }
    }
}

// ---------------- attention pre-scores layer 2 ----------------
__global__ void s2_kernel(const float* __restrict__ attn, int n) {
    int w = (blockIdx.x * blockDim.x + threadIdx.x) >> 5;
    int lane = threadIdx.x & 31;
    if (w >= n) return;
    const __half* z = d_Z2h + (size_t)w * HID;
    float z0 = __half2float(z[lane]);
    float z1 = __half2float(z[32 + lane]);
    float ps = z0 * attn[lane] + z1 * attn[32 + lane];
    float pd = z0 * attn[HID + lane] + z1 * attn[HID + 32 + lane];
#pragma unroll
    for (int o = 16; o; o >>= 1) {
        ps += __shfl_xor_sync(~0u, ps, o);
        pd += __shfl_xor_sync(~0u, pd, o);
    }
    if (lane == 0) { d_S2src[w] = ps; d_S2dst[w] = pd; }
}

// ---------------- CSR build ----------------
__global__ void hist_kernel(const int* __restrict__ dst, int e) {
    int i = blockIdx.x * blockDim.x + threadIdx.x;
    if (i < e) atomicAdd(&d_counts[dst[i]], 1);
}

__global__ void scan1_kernel(int n) {
    __shared__ int sm[1024];
    int i = blockIdx.x * 1024 + threadIdx.x;
    int x = (i < n) ? d_counts[i] : 0;
    sm[threadIdx.x] = x;
    __syncthreads();
    int val = x;
    for (int d = 1; d < 1024; d <<= 1) {
        int t = (threadIdx.x >= (unsigned)d) ? sm[threadIdx.x - d] : 0;
        __syncthreads();
        val += t;
        sm[threadIdx.x] = val;
        __syncthreads();
    }
    if (i < n) d_offs[i] = val - x;               // block-local exclusive
    if (threadIdx.x == 1023) d_blockSums[blockIdx.x] = val;
}

__global__ void scan2_kernel(int nb) {
    if (threadIdx.x == 0 && blockIdx.x == 0) {
        int acc = 0;
        for (int b = 0; b < nb; b++) { d_blockOffs[b] = acc; acc += d_blockSums[b]; }
    }
}

__global__ void scan3_kernel(int n, int e) {
    int i = blockIdx.x * blockDim.x + threadIdx.x;
    if (i < n) {
        int o = d_offs[i] + d_blockOffs[i >> 10];
        d_offs[i] = o;
        d_cursor[i] = o;   // pre-seeded cursor: fill uses a single atomic
    }
    if (i == 0) d_offs[n] = e;
}

__global__ void fill_kernel(const int* __restrict__ src, const int* __restrict__ dst, int e) {
    int i = blockIdx.x * blockDim.x + threadIdx.x;
    if (i < e) {
        int pos = atomicAdd(&d_cursor[dst[i]], 1);
        d_esrc[pos] = src[i];
    }
}

// ---------------- layer1 GAT aggregation (4 heads fused), warp per dst ----------------
// Softmax computed WITHOUT max-shift (scores are O(10); exp fits fp32 easily).
__global__ void agg1_kernel(int n) {
    int w = (blockIdx.x * blockDim.x + threadIdx.x) >> 5;
    int lane = threadIdx.x & 31;
    if (w >= n) return;
    int beg = d_offs[w], end = d_offs[w + 1];
    float4 sd4 = *(const float4*)(d_S1dst + w * 4);

    int myh = lane >> 3;  // lanes 0-7 head 0, 8-15 head 1, ...
    float sd = (myh == 0) ? sd4.x : (myh == 1) ? sd4.y : (myh == 2) ? sd4.z : sd4.w;

    // warp-serial over edges; lanes own 8 contiguous output cols (halves)
    float acc[8] = {0, 0, 0, 0, 0, 0, 0, 0};
    float den = 0.f;
    for (int e = beg; e < end; e++) {
        int s = d_esrc[e];                               // broadcast
        float sv = __ldg(d_S1src + s * 4 + myh);
        float wgt = __expf(lrelu(sv + sd));
        den += wgt;
        uint4 u = __ldg((const uint4*)(d_Z1h + (size_t)s * Z1DIM) + lane);  // 8 halves
        const __half2* hp = (const __half2*)&u;
#pragma unroll
        for (int q = 0; q < 4; q++) {
            float2 f = __half22float2(hp[q]);
            acc[2 * q]     += wgt * f.x;
            acc[2 * q + 1] += wgt * f.y;
        }
    }
    float inv = 1.f / den;
    uint4 outv;
    __half2* op = (__half2*)&outv;
#pragma unroll
    for (int q = 0; q < 4; q++) {
        float a = elu1(acc[2 * q] * inv);
        float b = elu1(acc[2 * q + 1] * inv);
        op[q] = __halves2half2(__float2half_rn(a), __float2half_rn(b));
    }
    *((uint4*)(d_H1h + (size_t)w * Z1DIM) + lane) = outv;
}

// ---------------- layer2 GAT aggregation -> column sum directly ----------------
__global__ void agg2_kernel(int n) {
    __shared__ float red[HID];
    int lt = threadIdx.x;
    if (lt < HID) red[lt] = 0.f;
    __syncthreads();
    int w = (blockIdx.x * blockDim.x + lt) >> 5;
    int lane = lt & 31;
    if (w < n) {
        int beg = d_offs[w], end = d_offs[w + 1];
        float sd = d_S2dst[w];
        float2 acc = make_float2(0, 0);
        float den = 0.f;
        for (int e = beg; e < end; e++) {
            int s = d_esrc[e];
            float wgt = __expf(lrelu(__ldg(d_S2src + s) + sd));
            den += wgt;
            __half2 zh = __ldg((const __half2*)(d_Z2h + (size_t)s * HID) + lane);
            float2 z = __half22float2(zh);
            acc.x += wgt * z.x;
            acc.y += wgt * z.y;
        }
        float inv = 1.f / den;
        atomicAdd(&red[lane * 2 + 0], acc.x * inv);
        atomicAdd(&red[lane * 2 + 1], acc.y * inv);
    }
    __syncthreads();
    if (lt < HID) atomicAdd(&d_sumH2[lt], red[lt]);
}

// ---------------- fractal branch: sum of gathered h rows per scale ----------------
__global__ void frac_kernel(const float* __restrict__ h, const int* __restrict__ fcm, int n) {
    int s = blockIdx.y;
    __shared__ float red[INDIM];
    int lt = threadIdx.x;
    if (lt < INDIM) red[lt] = 0.f;
    __syncthreads();
    int lane = lt & 31;
    float4 acc = make_float4(0, 0, 0, 0);
    int wg = (blockIdx.x * blockDim.x + lt) >> 5;
    int nw = (gridDim.x * blockDim.x) >> 5;
    for (int node = wg; node < n; node += nw) {
        int idx = __ldg(fcm + node * SCALES + s);
        float4 v = __ldg((const float4*)(h + (size_t)idx * INDIM) + lane);
        acc.x += v.x; acc.y += v.y; acc.z += v.z; acc.w += v.w;
    }
    atomicAdd(&red[lane * 4 + 0], acc.x);
    atomicAdd(&red[lane * 4 + 1], acc.y);
    atomicAdd(&red[lane * 4 + 2], acc.z);
    atomicAdd(&red[lane * 4 + 3], acc.w);
    __syncthreads();
    if (lt < INDIM) atomicAdd(&d_fracsum[s * INDIM + lt], red[lt]);
}

// ---------------- final combine (all linear post-softmax work) ----------------
__global__ void final_kernel(const float* __restrict__ frac_w,
                             const float* __restrict__ frac_final_w,
                             const float* __restrict__ fc2_w,
                             float* __restrict__ out, int n) {
    __shared__ float y[SCALES * HID];   // mean of frac intermediate [192]
    __shared__ float mh[HID];           // mean of H2
    __shared__ float mf[HID];           // mean of h_frac
    int t = threadIdx.x;                // 64 threads
    float invn = 1.f / (float)n;
    mh[t] = d_sumH2[t] * invn;
#pragma unroll
    for (int s = 0; s < SCALES; s++) {
        const float* wrow = frac_w + (size_t)(s * HID + t) * INDIM;
        const float* g = d_fracsum + s * INDIM;
        float acc = 0.f;
        for (int k = 0; k < INDIM; k++) acc += wrow[k] * g[k];
        y[s * HID + t] = acc * invn;
    }
    __syncthreads();
    {
        const float* fr = frac_final_w + (size_t)t * (SCALES * HID);
        float acc = 0.f;
        for (int k = 0; k < SCALES * HID; k++) acc += fr[k] * y[k];
        mf[t] = acc;
    }
    __syncthreads();
    {
        const float* w2 = fc2_w + (size_t)t * (2 * HID);
        float o = 0.f;
        for (int k = 0; k < HID; k++) o += w2[k] * mh[k];
        for (int k = 0; k < HID; k++) o += w2[HID + k] * mf[k];
        out[t] = o;
    }
}

// ---------------- launch ----------------
extern "C" void kernel_launch(void* const* d_in, const int* in_sizes, int n_in,
                              void* d_out, int out_size) {
    const float* h      = (const float*)d_in[0];
    const int*   src    = (const int*)d_in[1];
    const int*   dst    = (const int*)d_in[2];
    const int*   fcm    = (const int*)d_in[3];
    const float* l1fc   = (const float*)d_in[4];  // [4,64,128] -> [256,128]
    const float* l1attn = (const float*)d_in[5];  // [4,128]
    const float* l2fc   = (const float*)d_in[6];  // [64,256]
    const float* l2attn = (const float*)d_in[7];  // [128]
    const float* frw    = (const float*)d_in[8];  // [3,64,128]
    const float* frfw   = (const float*)d_in[9];  // [64,192]
    const float* fc2    = (const float*)d_in[10]; // [64,128]
    float* out = (float*)d_out;

    int n = in_sizes[0] / INDIM;   // 100000
    int e = in_sizes[1];           // 1700000

    __half *z1p, *h1p, *z2p;
    cudaGetSymbolAddress((void**)&z1p, d_Z1h);
    cudaGetSymbolAddress((void**)&h1p, d_H1h);
    cudaGetSymbolAddress((void**)&z2p, d_Z2h);

    int tpb = 256;
    int nWarpBlocks = (n * 32 + tpb - 1) / tpb;
    int nEdgeBlocks = (e + tpb - 1) / tpb;
    int nNodeBlocks = (n + tpb - 1) / tpb;
    int nb = (n + 1023) / 1024;

    // smem sizes for the two GEMM instantiations
    const int SM1 = (64 * (INDIM + 8) + Z1DIM * (INDIM + 8)) * 2;   // 87,040 B
    const int SM2 = (128 * (Z1DIM + 8) + HID * (Z1DIM + 8)) * 2;    // 101,376 B
    cudaFuncSetAttribute((const void*)gemm_tc<64, Z1DIM, INDIM, float>,
                         cudaFuncAttributeMaxDynamicSharedMemorySize, SM1);
    cudaFuncSetAttribute((const void*)gemm_tc<128, HID, Z1DIM, __half>,
                         cudaFuncAttributeMaxDynamicSharedMemorySize, SM2);

    // 0. zero scratch (counts/sums)
    zero_kernel<<<nNodeBlocks, tpb>>>(n);

    // 1. Z1 = h @ W1cat^T   [n,128] x [256,128]^T  (tensor cores, fp16 out)
    gemm_tc<64, Z1DIM, INDIM, float><<<(n + 63) / 64, 256, SM1>>>(h, l1fc, z1p, n);

    // 2. per-node attention pre-scores (layer 1)
    s1_kernel<<<nWarpBlocks, tpb>>>(l1attn, n);

    // 3. CSR build (sorted by dst)
    hist_kernel<<<nEdgeBlocks, tpb>>>(dst, e);
    scan1_kernel<<<nb, 1024>>>(n);
    scan2_kernel<<<1, 32>>>(nb);
    scan3_kernel<<<nNodeBlocks, tpb>>>(n, e);
    fill_kernel<<<nEdgeBlocks, tpb>>>(src, dst, e);

    // 4. layer-1 GAT aggregation -> H1 (elu applied, fp16)
    agg1_kernel<<<nWarpBlocks, tpb>>>(n);

    // 5. Z2 = H1 @ layer2_fc^T   [n,256] x [64,256]^T  (tensor cores)
    gemm_tc<128, HID, Z1DIM, __half><<<(n + 127) / 128, 256, SM2>>>(h1p, l2fc, z2p, n);

    // 6. per-node attention pre-scores (layer 2)
    s2_kernel<<<nWarpBlocks, tpb>>>(l2attn, n);

    // 7. layer-2 GAT aggregation -> column sums of H2 only
    agg2_kernel<<<nWarpBlocks, tpb>>>(n);

    // 8. fractal branch gather-sums
    {
        dim3 grid(128, SCALES);
        frac_kernel<<<grid, tpb>>>(h, fcm, n);
    }

    // 9. final linear combine + mean
    final_kernel<<<1, HID>>>(frw, frfw, fc2, out, n);
}

// round 4
// speedup vs baseline: 1.7509x; 1.0532x over previous
#include <cuda_runtime.h>
#include <cuda_fp16.h>
#include <math.h>

#define NNODES 100000
#define EMAX   1700000
#define INDIM  128
#define HID    64
#define HEADS  4
#define Z1DIM  (HID*HEADS)   // 256
#define SCALES 3

// ---------------- device scratch ----------------
__device__ __align__(16) __half d_Z1h[(size_t)NNODES * Z1DIM];
__device__ __align__(16) __half d_H1h[(size_t)NNODES * Z1DIM];
__device__ __align__(16) __half d_Z2h[(size_t)NNODES * HID];
__device__ float d_S1src[NNODES * HEADS];
__device__ float d_S1dst[NNODES * HEADS];
__device__ float d_S2src[NNODES];
__device__ float d_S2dst[NNODES];
__device__ int   d_counts[NNODES];
__device__ int   d_cursor[NNODES];
__device__ int   d_offs[NNODES + 1];
__device__ int   d_esrc[EMAX];
__device__ int   d_blockSums[256];
__device__ int   d_blockOffs[256];
__device__ float d_sumH2[HID];
__device__ float d_fracsum[SCALES * INDIM];

// ---------------- helpers ----------------
__device__ __forceinline__ float lrelu(float x) { return x > 0.f ? x : 0.01f * x; }
__device__ __forceinline__ float elu1(float x)  { return x > 0.f ? x : expm1f(x); }

// ---------------- zero scratch ----------------
__global__ void zero_kernel(int n) {
    int i = blockIdx.x * blockDim.x + threadIdx.x;
    if (i < n) d_counts[i] = 0;
    if (i < HID) d_sumH2[i] = 0.f;
    if (i < SCALES * INDIM) d_fracsum[i] = 0.f;
}

// ---------------- Tensor-core GEMM with fused attention-score epilogue ----------------
// C[M,BN](half) = A[M,KK] * B[BN,KK]^T.  Whole K & N in smem, one load, MMA sweep.
// MODE 0: plain.  MODE 1: also emit S1src/S1dst (4 heads of 64 cols).  MODE 2: S2 (1 head).
template <int BM, int BN, int KK, int MODE, typename TA>
__global__ __launch_bounds__(256) void gemm_tc(const TA* __restrict__ A,
                                               const float* __restrict__ B,
                                               __half* __restrict__ C,
                                               const float* __restrict__ attn,
                                               float* __restrict__ ps_out,
                                               float* __restrict__ pd_out,
                                               int M) {
    constexpr int LDA = KK + 8;
    constexpr int M_WARPS = BM / 32;
    constexpr int N_WARPS = 8 / M_WARPS;
    constexpr int WN = BN / N_WARPS;
    constexpr int M_FRAGS = 2;
    constexpr int N_FRAGS = WN / 8;
    constexpr int NH = (MODE == 1) ? HEADS : 1;

    extern __shared__ __half smem[];
    __half* As = smem;
    __half* Bs = smem + BM * LDA;
    float* score = (float*)(smem + (BM + BN) * LDA);  // [2][BM][NH]

    int tid = threadIdx.x;
    int lane = tid & 31;
    int wid = tid >> 5;
    int wm = (wid % M_WARPS) * 32;
    int wn = (wid / M_WARPS) * WN;
    int m0 = blockIdx.x * BM;

    if (MODE) {
        for (int i = tid; i < 2 * BM * NH; i += 256) score[i] = 0.f;
    }

    constexpr int A_ITERS = BM * KK / (256 * 8);
#pragma unroll
    for (int it = 0; it < A_ITERS; it++) {
        int idx = (it * 256 + tid) * 8;
        int row = idx / KK, col = idx % KK;
        int grow = m0 + row;
        uint4 u;
        if (grow < M) {
            if constexpr (sizeof(TA) == 4) {
                const float* p = (const float*)A + (size_t)grow * KK + col;
                float4 v0 = *(const float4*)p;
                float4 v1 = *(const float4*)(p + 4);
                __half2 h0 = __floats2half2_rn(v0.x, v0.y);
                __half2 h1 = __floats2half2_rn(v0.z, v0.w);
                __half2 h2 = __floats2half2_rn(v1.x, v1.y);
                __half2 h3 = __floats2half2_rn(v1.z, v1.w);
                u = make_uint4(*(unsigned*)&h0, *(unsigned*)&h1, *(unsigned*)&h2, *(unsigned*)&h3);
            } else {
                u = *(const uint4*)((const __half*)A + (size_t)grow * KK + col);
            }
        } else {
            u = make_uint4(0, 0, 0, 0);
        }
        *(uint4*)&As[row * LDA + col] = u;
    }

    constexpr int B_ITERS = BN * KK / (256 * 8);
#pragma unroll
    for (int it = 0; it < B_ITERS; it++) {
        int idx = (it * 256 + tid) * 8;
        int row = idx / KK, col = idx % KK;
        const float* p = B + (size_t)row * KK + col;
        float4 v0 = *(const float4*)p;
        float4 v1 = *(const float4*)(p + 4);
        __half2 h0 = __floats2half2_rn(v0.x, v0.y);
        __half2 h1 = __floats2half2_rn(v0.z, v0.w);
        __half2 h2 = __floats2half2_rn(v1.x, v1.y);
        __half2 h3 = __floats2half2_rn(v1.z, v1.w);
        *(uint4*)&Bs[row * LDA + col] = make_uint4(*(unsigned*)&h0, *(unsigned*)&h1,
                                                   *(unsigned*)&h2, *(unsigned*)&h3);
    }
    __syncthreads();

    float acc[M_FRAGS][N_FRAGS][4];
#pragma unroll
    for (int f = 0; f < M_FRAGS; f++)
#pragma unroll
        for (int g = 0; g < N_FRAGS; g++)
#pragma unroll
            for (int q = 0; q < 4; q++) acc[f][g][q] = 0.f;

    int lr = lane >> 2;
    int lc = (lane & 3) * 2;

#pragma unroll
    for (int ks = 0; ks < KK / 16; ks++) {
        unsigned a[M_FRAGS][4];
#pragma unroll
        for (int f = 0; f < M_FRAGS; f++) {
            const __half* pa = As + (wm + f * 16 + lr) * LDA + ks * 16 + lc;
            a[f][0] = *(const unsigned*)pa;
            a[f][1] = *(const unsigned*)(pa + 8 * LDA);
            a[f][2] = *(const unsigned*)(pa + 8);
            a[f][3] = *(const unsigned*)(pa + 8 * LDA + 8);
        }
        unsigned b[N_FRAGS][2];
#pragma unroll
        for (int g = 0; g < N_FRAGS; g++) {
            const __half* pb = Bs + (wn + g * 8 + lr) * LDA + ks * 16 + lc;
            b[g][0] = *(const unsigned*)pb;
            b[g][1] = *(const unsigned*)(pb + 8);
        }
#pragma unroll
        for (int f = 0; f < M_FRAGS; f++)
#pragma unroll
            for (int g = 0; g < N_FRAGS; g++) {
                asm volatile(
                    "mma.sync.aligned.m16n8k16.row.col.f32.f16.f16.f32 "
                    "{%0,%1,%2,%3}, {%4,%5,%6,%7}, {%8,%9}, {%0,%1,%2,%3};"
                    : "+f"(acc[f][g][0]), "+f"(acc[f][g][1]),
                      "+f"(acc[f][g][2]), "+f"(acc[f][g][3])
                    : "r"(a[f][0]), "r"(a[f][1]), "r"(a[f][2]), "r"(a[f][3]),
                      "r"(b[g][0]), "r"(b[g][1]));
            }
    }

    // ---- epilogue: C writes ----
#pragma unroll
    for (int f = 0; f < M_FRAGS; f++) {
        int row = m0 + wm + f * 16 + lr;
#pragma unroll
        for (int g = 0; g < N_FRAGS; g++) {
            int col = wn + g * 8 + lc;
            if (row < M) {
                __half2 v = __floats2half2_rn(acc[f][g][0], acc[f][g][1]);
                *(__half2*)&C[(size_t)row * BN + col] = v;
            }
            if (row + 8 < M) {
                __half2 v = __floats2half2_rn(acc[f][g][2], acc[f][g][3]);
                *(__half2*)&C[(size_t)(row + 8) * BN + col] = v;
            }
        }
    }

    // ---- fused attention pre-score epilogue ----
    if (MODE) {
        int hd = (MODE == 1) ? (wn / HID) : 0;        // head this warp covers
        float psum[2 * M_FRAGS], pdsum[2 * M_FRAGS];
#pragma unroll
        for (int q = 0; q < 2 * M_FRAGS; q++) { psum[q] = 0.f; pdsum[q] = 0.f; }
#pragma unroll
        for (int g = 0; g < N_FRAGS; g++) {
            int cH = (MODE == 1) ? (g * 8 + lc) : (wn + g * 8 + lc);
            const float* ah = attn + hd * 2 * HID;
            float a0 = __ldg(ah + cH), a1 = __ldg(ah + cH + 1);
            float d0 = __ldg(ah + HID + cH), d1 = __ldg(ah + HID + cH + 1);
#pragma unroll
            for (int f = 0; f < M_FRAGS; f++) {
                psum[f * 2 + 0] += acc[f][g][0] * a0 + acc[f][g][1] * a1;
                psum[f * 2 + 1] += acc[f][g][2] * a0 + acc[f][g][3] * a1;
                pdsum[f * 2 + 0] += acc[f][g][0] * d0 + acc[f][g][1] * d1;
                pdsum[f * 2 + 1] += acc[f][g][2] * d0 + acc[f][g][3] * d1;
            }
        }
#pragma unroll
        for (int f = 0; f < M_FRAGS; f++) {
            int rl = wm + f * 16 + lr;
            atomicAdd(&score[rl * NH + hd], psum[f * 2 + 0]);
            atomicAdd(&score[(rl + 8) * NH + hd], psum[f * 2 + 1]);
            atomicAdd(&score[BM * NH + rl * NH + hd], pdsum[f * 2 + 0]);
            atomicAdd(&score[BM * NH + (rl + 8) * NH + hd], pdsum[f * 2 + 1]);
        }
        __syncthreads();
        for (int i = tid; i < BM * NH; i += 256) {
            int row = i / NH;
            int node = m0 + row;
            if (node < M) {
                int o = (MODE == 1) ? (node * NH + (i % NH)) : node;
                ps_out[o] = score[i];
                pd_out[o] = score[BM * NH + i];
            }
        }
    }
}

// ---------------- CSR build ----------------
__global__ void hist_kernel(const int* __restrict__ dst, int e) {
    int i = blockIdx.x * blockDim.x + threadIdx.x;
    if (i < e) atomicAdd(&d_counts[dst[i]], 1);
}

__global__ void scan1_kernel(int n) {
    __shared__ int sm[1024];
    int i = blockIdx.x * 1024 + threadIdx.x;
    int x = (i < n) ? d_counts[i] : 0;
    sm[threadIdx.x] = x;
    __syncthreads();
    int val = x;
    for (int d = 1; d < 1024; d <<= 1) {
        int t = (threadIdx.x >= (unsigned)d) ? sm[threadIdx.x - d] : 0;
        __syncthreads();
        val += t;
        sm[threadIdx.x] = val;
        __syncthreads();
    }
    if (i < n) d_offs[i] = val - x;
    if (threadIdx.x == 1023) d_blockSums[blockIdx.x] = val;
}

__global__ void scan2_kernel(int nb) {
    if (threadIdx.x == 0 && blockIdx.x == 0) {
        int acc = 0;
        for (int b = 0; b < nb; b++) { d_blockOffs[b] = acc; acc += d_blockSums[b]; }
    }
}

__global__ void scan3_kernel(int n, int e) {
    int i = blockIdx.x * blockDim.x + threadIdx.x;
    if (i < n) {
        int o = d_offs[i] + d_blockOffs[i >> 10];
        d_offs[i] = o;
        d_cursor[i] = o;
    }
    if (i == 0) d_offs[n] = e;
}

__global__ void fill_kernel(const int* __restrict__ src, const int* __restrict__ dst, int e) {
    int i = blockIdx.x * blockDim.x + threadIdx.x;
    if (i < e) {
        int pos = atomicAdd(&d_cursor[dst[i]], 1);
        d_esrc[pos] = src[i];
    }
}

// ---------------- layer1 aggregation: warp per dst, 4-way pipelined ----------------
__global__ void agg1_kernel(int n) {
    int w = (blockIdx.x * blockDim.x + threadIdx.x) >> 5;
    int lane = threadIdx.x & 31;
    if (w >= n) return;
    int beg = d_offs[w], end = d_offs[w + 1];
    int myh = lane >> 3;
    float sd = __ldg(d_S1dst + w * 4 + myh);

    float acc[8] = {0, 0, 0, 0, 0, 0, 0, 0};
    float den = 0.f;
    int e = beg;
    for (; e + 4 <= end; e += 4) {
        int s0 = __ldg(d_esrc + e + 0);
        int s1 = __ldg(d_esrc + e + 1);
        int s2 = __ldg(d_esrc + e + 2);
        int s3 = __ldg(d_esrc + e + 3);
        float v0 = __ldg(d_S1src + s0 * 4 + myh);
        float v1 = __ldg(d_S1src + s1 * 4 + myh);
        float v2 = __ldg(d_S1src + s2 * 4 + myh);
        float v3 = __ldg(d_S1src + s3 * 4 + myh);
        uint4 u0 = __ldg((const uint4*)(d_Z1h + (size_t)s0 * Z1DIM) + lane);
        uint4 u1 = __ldg((const uint4*)(d_Z1h + (size_t)s1 * Z1DIM) + lane);
        uint4 u2 = __ldg((const uint4*)(d_Z1h + (size_t)s2 * Z1DIM) + lane);
        uint4 u3 = __ldg((const uint4*)(d_Z1h + (size_t)s3 * Z1DIM) + lane);
        uint4 us[4] = {u0, u1, u2, u3};
        float vs[4] = {v0, v1, v2, v3};
#pragma unroll
        for (int k = 0; k < 4; k++) {
            float wg = __expf(lrelu(vs[k] + sd));
            den += wg;
            const __half2* hp = (const __half2*)&us[k];
#pragma unroll
            for (int q = 0; q < 4; q++) {
                float2 f = __half22float2(hp[q]);
                acc[2 * q]     += wg * f.x;
                acc[2 * q + 1] += wg * f.y;
            }
        }
    }
    for (; e < end; e++) {
        int s = __ldg(d_esrc + e);
        float sv = __ldg(d_S1src + s * 4 + myh);
        float wg = __expf(lrelu(sv + sd));
        den += wg;
        uint4 u = __ldg((const uint4*)(d_Z1h + (size_t)s * Z1DIM) + lane);
        const __half2* hp = (const __half2*)&u;
#pragma unroll
        for (int q = 0; q < 4; q++) {
            float2 f = __half22float2(hp[q]);
            acc[2 * q]     += wg * f.x;
            acc[2 * q + 1] += wg * f.y;
        }
    }
    float inv = 1.f / den;
    uint4 outv;
    __half2* op = (__half2*)&outv;
#pragma unroll
    for (int q = 0; q < 4; q++) {
        float a = elu1(acc[2 * q] * inv);
        float b = elu1(acc[2 * q + 1] * inv);
        op[q] = __halves2half2(__float2half_rn(a), __float2half_rn(b));
    }
    *((uint4*)(d_H1h + (size_t)w * Z1DIM) + lane) = outv;
}

// ---------------- layer2 aggregation: grid-stride warps, column-sum output ----------------
__global__ void agg2_kernel(int n) {
    __shared__ float red[HID];
    int lt = threadIdx.x;
    if (lt < HID) red[lt] = 0.f;
    __syncthreads();
    int lane = lt & 31;
    int gw = (blockIdx.x * blockDim.x + lt) >> 5;
    int nw = (gridDim.x * blockDim.x) >> 5;
    float2 tot = make_float2(0.f, 0.f);
    for (int w = gw; w < n; w += nw) {
        int beg = d_offs[w], end = d_offs[w + 1];
        float sd = __ldg(d_S2dst + w);
        float2 acc = make_float2(0.f, 0.f);
        float den = 0.f;
        int e = beg;
        for (; e + 4 <= end; e += 4) {
            int s0 = __ldg(d_esrc + e + 0);
            int s1 = __ldg(d_esrc + e + 1);
            int s2 = __ldg(d_esrc + e + 2);
            int s3 = __ldg(d_esrc + e + 3);
            float v0 = __ldg(d_S2src + s0);
            float v1 = __ldg(d_S2src + s1);
            float v2 = __ldg(d_S2src + s2);
            float v3 = __ldg(d_S2src + s3);
            __half2 z0 = __ldg((const __half2*)(d_Z2h + (size_t)s0 * HID) + lane);
            __half2 z1 = __ldg((const __half2*)(d_Z2h + (size_t)s1 * HID) + lane);
            __half2 z2 = __ldg((const __half2*)(d_Z2h + (size_t)s2 * HID) + lane);
            __half2 z3 = __ldg((const __half2*)(d_Z2h + (size_t)s3 * HID) + lane);
            __half2 zs[4] = {z0, z1, z2, z3};
            float vs[4] = {v0, v1, v2, v3};
#pragma unroll
            for (int k = 0; k < 4; k++) {
                float wg = __expf(lrelu(vs[k] + sd));
                den += wg;
                float2 f = __half22float2(zs[k]);
                acc.x += wg * f.x;
                acc.y += wg * f.y;
            }
        }
        for (; e < end; e++) {
            int s = __ldg(d_esrc + e);
            float wg = __expf(lrelu(__ldg(d_S2src + s) + sd));
            den += wg;
            float2 f = __half22float2(__ldg((const __half2*)(d_Z2h + (size_t)s * HID) + lane));
            acc.x += wg * f.x;
            acc.y += wg * f.y;
        }
        float inv = 1.f / den;
        tot.x += acc.x * inv;
        tot.y += acc.y * inv;
    }
    atomicAdd(&red[lane * 2 + 0], tot.x);
    atomicAdd(&red[lane * 2 + 1], tot.y);
    __syncthreads();
    if (lt < HID) atomicAdd(&d_sumH2[lt], red[lt]);
}

// ---------------- fractal branch: gather-sum per scale ----------------
__global__ void frac_kernel(const float* __restrict__ h, const int* __restrict__ fcm, int n) {
    int s = blockIdx.y;
    __shared__ float red[INDIM];
    int lt = threadIdx.x;
    if (lt < INDIM) red[lt] = 0.f;
    __syncthreads();
    int lane = lt & 31;
    float4 acc = make_float4(0, 0, 0, 0);
    int wg = (blockIdx.x * blockDim.x + lt) >> 5;
    int nw = (gridDim.x * blockDim.x) >> 5;
    for (int node = wg; node < n; node += nw) {
        int idx = __ldg(fcm + node * SCALES + s);
        float4 v = __ldg((const float4*)(h + (size_t)idx * INDIM) + lane);
        acc.x += v.x; acc.y += v.y; acc.z += v.z; acc.w += v.w;
    }
    atomicAdd(&red[lane * 4 + 0], acc.x);
    atomicAdd(&red[lane * 4 + 1], acc.y);
    atomicAdd(&red[lane * 4 + 2], acc.z);
    atomicAdd(&red[lane * 4 + 3], acc.w);
    __syncthreads();
    if (lt < INDIM) atomicAdd(&d_fracsum[s * INDIM + lt], red[lt]);
}

// ---------------- final combine ----------------
__global__ void final_kernel(const float* __restrict__ frac_w,
                             const float* __restrict__ frac_final_w,
                             const float* __restrict__ fc2_w,
                             float* __restrict__ out, int n) {
    __shared__ float y[SCALES * HID];
    __shared__ float mh[HID];
    __shared__ float mf[HID];
    int t = threadIdx.x;
    float invn = 1.f / (float)n;
    mh[t] = d_sumH2[t] * invn;
#pragma unroll
    for (int s = 0; s < SCALES; s++) {
        const float* wrow = frac_w + (size_t)(s * HID + t) * INDIM;
        const float* g = d_fracsum + s * INDIM;
        float acc = 0.f;
        for (int k = 0; k < INDIM; k++) acc += wrow[k] * g[k];
        y[s * HID + t] = acc * invn;
    }
    __syncthreads();
    {
        const float* fr = frac_final_w + (size_t)t * (SCALES * HID);
        float acc = 0.f;
        for (int k = 0; k < SCALES * HID; k++) acc += fr[k] * y[k];
        mf[t] = acc;
    }
    __syncthreads();
    {
        const float* w2 = fc2_w + (size_t)t * (2 * HID);
        float o = 0.f;
        for (int k = 0; k < HID; k++) o += w2[k] * mh[k];
        for (int k = 0; k < HID; k++) o += w2[HID + k] * mf[k];
        out[t] = o;
    }
}

// ---------------- launch ----------------
extern "C" void kernel_launch(void* const* d_in, const int* in_sizes, int n_in,
                              void* d_out, int out_size) {
    const float* h      = (const float*)d_in[0];
    const int*   src    = (const int*)d_in[1];
    const int*   dst    = (const int*)d_in[2];
    const int*   fcm    = (const int*)d_in[3];
    const float* l1fc   = (const float*)d_in[4];
    const float* l1attn = (const float*)d_in[5];
    const float* l2fc   = (const float*)d_in[6];
    const float* l2attn = (const float*)d_in[7];
    const float* frw    = (const float*)d_in[8];
    const float* frfw   = (const float*)d_in[9];
    const float* fc2    = (const float*)d_in[10];
    float* out = (float*)d_out;

    int n = in_sizes[0] / INDIM;   // 100000
    int e = in_sizes[1];           // 1700000

    __half *z1p, *h1p, *z2p;
    float *s1s, *s1d, *s2s, *s2d;
    cudaGetSymbolAddress((void**)&z1p, d_Z1h);
    cudaGetSymbolAddress((void**)&h1p, d_H1h);
    cudaGetSymbolAddress((void**)&z2p, d_Z2h);
    cudaGetSymbolAddress((void**)&s1s, d_S1src);
    cudaGetSymbolAddress((void**)&s1d, d_S1dst);
    cudaGetSymbolAddress((void**)&s2s, d_S2src);
    cudaGetSymbolAddress((void**)&s2d, d_S2dst);

    int tpb = 256;
    int nWarpBlocks = (n * 32 + tpb - 1) / tpb;
    int nEdgeBlocks = (e + tpb - 1) / tpb;
    int nNodeBlocks = (n + tpb - 1) / tpb;
    int nb = (n + 1023) / 1024;

    const int SM1 = (64 + Z1DIM) * (INDIM + 8) * 2 + 2 * 64 * HEADS * 4;   // 89,088 B
    const int SM2 = (128 + HID) * (Z1DIM + 8) * 2 + 2 * 128 * 4;           // 102,400 B
    cudaFuncSetAttribute((const void*)gemm_tc<64, Z1DIM, INDIM, 1, float>,
                         cudaFuncAttributeMaxDynamicSharedMemorySize, SM1);
    cudaFuncSetAttribute((const void*)gemm_tc<128, HID, Z1DIM, 2, __half>,
                         cudaFuncAttributeMaxDynamicSharedMemorySize, SM2);

    // 1. zero scratch
    zero_kernel<<<nNodeBlocks, tpb>>>(n);
    // 2. edge histogram
    hist_kernel<<<nEdgeBlocks, tpb>>>(dst, e);
    // 3. scan part 1
    scan1_kernel<<<nb, 1024>>>(n);
    // 4. GEMM1 + fused S1 scores   (ncu capture slot)
    gemm_tc<64, Z1DIM, INDIM, 1, float><<<(n + 63) / 64, 256, SM1>>>(
        h, l1fc, z1p, l1attn, s1s, s1d, n);
    // 5-7. finish CSR
    scan2_kernel<<<1, 32>>>(nb);
    scan3_kernel<<<nNodeBlocks, tpb>>>(n, e);
    fill_kernel<<<nEdgeBlocks, tpb>>>(src, dst, e);
    // 8. layer-1 aggregation
    agg1_kernel<<<nWarpBlocks, tpb>>>(n);
    // 9. GEMM2 + fused S2 scores
    gemm_tc<128, HID, Z1DIM, 2, __half><<<(n + 127) / 128, 256, SM2>>>(
        h1p, l2fc, z2p, l2attn, s2s, s2d, n);
    // 10. layer-2 aggregation -> column sums
    agg2_kernel<<<1184, tpb>>>(n);
    // 11. fractal gather-sums
    {
        dim3 grid(512, SCALES);
        frac_kernel<<<grid, tpb>>>(h, fcm, n);
    }
    // 12. final combine
    final_kernel<<<1, HID>>>(frw, frfw, fc2, out, n);
}